// round 7
// baseline (speedup 1.0000x reference)
#include <cuda_runtime.h>
#include <cstdint>
#include <cstddef>

#define BATCH 256
#define ANUM  128
#define NBNUM 256
#define DNUM  16
#define FA    64
#define FB    32
#define FPC   256
#define R_NEI  (BATCH*ANUM*DNUM)   // 524288
#define R_ATOM (BATCH*ANUM)        // 32768
#define R_BOND (BATCH*NBNUM)       // 65536
#define ATOM_OUT_ELEMS ((long long)R_ATOM*FPC)
#define NEI_OUT_ELEMS  ((long long)R_NEI*FPC)
#define BN_EPS 1e-6f
#define SLOPE  0.01f

// ---------------- device scratch ----------------
__device__ float g_P[(size_t)R_ATOM * FPC];   // 33.5 MB
__device__ float g_Q[(size_t)R_BOND * FPC];   // 67 MB
__device__ float g_cntA[R_ATOM];
__device__ float g_cntB[R_BOND];
__device__ float g_Sab[64*32];
__device__ float g_sum[2][FPC];
__device__ float g_sqsum[2][FPC];
__device__ float g_scale[2][FPC];
__device__ float g_shift[2][FPC];

// ---------------- packed f32x2 helpers ----------------
__device__ __forceinline__ unsigned long long pack2(float lo, float hi) {
    unsigned long long r;
    asm("mov.b64 %0, {%1,%2};" : "=l"(r) : "f"(lo), "f"(hi));
    return r;
}
__device__ __forceinline__ void fma2(unsigned long long& d,
                                     unsigned long long a,
                                     unsigned long long b) {
    asm("fma.rn.f32x2 %0, %1, %2, %0;" : "+l"(d) : "l"(a), "l"(b));
}
__device__ __forceinline__ float2 unpack2(unsigned long long v) {
    float2 r;
    asm("mov.b64 {%0,%1}, %2;" : "=f"(r.x), "=f"(r.y) : "l"(v));
    return r;
}

// ---------------- prelude: per-batch count histograms + zero --------------
__global__ __launch_bounds__(256)
void prelude_kernel(const int* __restrict__ nl, const int* __restrict__ bl) {
    const int tid = threadIdx.x;
    if (blockIdx.x == BATCH) {      // zero block
        for (int i = tid; i < 64*32; i += 256) g_Sab[i] = 0.f;
        g_sum[0][tid] = 0.f; g_sum[1][tid] = 0.f;
        g_sqsum[0][tid] = 0.f; g_sqsum[1][tid] = 0.f;
        return;
    }
    __shared__ float hA[ANUM];
    __shared__ float hB[NBNUM];
    const int b = blockIdx.x;
    if (tid < ANUM) hA[tid] = 0.f;
    hB[tid] = 0.f;
    __syncthreads();
    const int base = b * (ANUM * DNUM);
    for (int i = tid; i < ANUM * DNUM; i += 256) {
        atomicAdd(&hA[nl[base + i]], 1.f);
        atomicAdd(&hB[bl[base + i]], 1.f);
    }
    __syncthreads();
    if (tid < ANUM) g_cntA[b * ANUM + tid] = hA[tid];
    g_cntB[b * NBNUM + tid] = hB[tid];
}

// ---------------- GEMM tile body (device) --------------------------------
// SMODE: 0 = none, 1 = plain stats -> slot 0, 2 = cnt-weighted -> slot 1
template<int K, int SMODE>
__device__ __forceinline__
void gemm_body(float* smem,
               const float4* __restrict__ Wg, int wldq, int woffq,
               const float4* __restrict__ X, const float* __restrict__ cnt,
               float* __restrict__ out, int tile)
{
    constexpr int KQ = K / 4;
    float* ws = smem;               // K*256
    float* xs = smem + K * FPC;     // K*64
    float* cw   = xs + K * 64;      // 64
    float* ssum = cw + 64;          // 256
    float* ssq  = ssum + FPC;       // 256

    const int tid = threadIdx.x;
    const int r0 = (tid >> 5) * 8;
    const int c0 = (tid & 31) * 8;

    for (int idx = tid; idx < FPC * KQ; idx += 256) {
        int q = idx >> 8;
        int c = idx & 255;
        float4 v = Wg[(size_t)c * wldq + woffq + q];
        ws[(4*q+0)*FPC + c] = v.x;
        ws[(4*q+1)*FPC + c] = v.y;
        ws[(4*q+2)*FPC + c] = v.z;
        ws[(4*q+3)*FPC + c] = v.w;
    }
    for (int idx = tid; idx < 64 * KQ; idx += 256) {
        int lr = idx & 63;
        int q  = idx >> 6;
        float4 v = X[(size_t)(tile * 64 + lr) * KQ + q];
        xs[(4*q+0)*64 + lr] = v.x;
        xs[(4*q+1)*64 + lr] = v.y;
        xs[(4*q+2)*64 + lr] = v.z;
        xs[(4*q+3)*64 + lr] = v.w;
    }
    if (SMODE == 2 && tid < 64) cw[tid] = cnt[tile * 64 + tid];
    __syncthreads();

    unsigned long long acc[8][4];
    #pragma unroll
    for (int i = 0; i < 8; ++i)
        #pragma unroll
        for (int j = 0; j < 4; ++j) acc[i][j] = 0ull;

    #pragma unroll 2
    for (int k = 0; k < K; ++k) {
        const float4 xa = *(const float4*)&xs[k*64 + r0];
        const float4 xb = *(const float4*)&xs[k*64 + r0 + 4];
        const ulonglong2 w0 = *(const ulonglong2*)&ws[k*FPC + c0];
        const ulonglong2 w1 = *(const ulonglong2*)&ws[k*FPC + c0 + 4];
        unsigned long long xp[8];
        xp[0] = pack2(xa.x, xa.x); xp[1] = pack2(xa.y, xa.y);
        xp[2] = pack2(xa.z, xa.z); xp[3] = pack2(xa.w, xa.w);
        xp[4] = pack2(xb.x, xb.x); xp[5] = pack2(xb.y, xb.y);
        xp[6] = pack2(xb.z, xb.z); xp[7] = pack2(xb.w, xb.w);
        #pragma unroll
        for (int i = 0; i < 8; ++i) {
            fma2(acc[i][0], xp[i], w0.x);
            fma2(acc[i][1], xp[i], w0.y);
            fma2(acc[i][2], xp[i], w1.x);
            fma2(acc[i][3], xp[i], w1.y);
        }
    }

    float sumc[8], sqc[8];
    if (SMODE > 0) {
        #pragma unroll
        for (int j = 0; j < 8; ++j) { sumc[j] = 0.f; sqc[j] = 0.f; }
    }

    #pragma unroll
    for (int i = 0; i < 8; ++i) {
        float y[8];
        #pragma unroll
        for (int j = 0; j < 4; ++j) {
            float2 p = unpack2(acc[i][j]);
            y[2*j]   = p.x;
            y[2*j+1] = p.y;
        }
        if (SMODE == 1) {
            #pragma unroll
            for (int j = 0; j < 8; ++j) { sumc[j] += y[j]; sqc[j] += y[j]*y[j]; }
        } else if (SMODE == 2) {
            float c = cw[r0 + i];
            #pragma unroll
            for (int j = 0; j < 8; ++j) { sumc[j] += c*y[j]; sqc[j] += c*y[j]*y[j]; }
        }
        size_t row = (size_t)tile * 64 + r0 + i;
        float4* o = (float4*)&out[row * FPC + c0];
        o[0] = make_float4(y[0], y[1], y[2], y[3]);
        o[1] = make_float4(y[4], y[5], y[6], y[7]);
    }

    if (SMODE > 0) {
        const int si = (SMODE == 1) ? 0 : 1;
        __syncthreads();
        ssum[tid] = 0.f; ssq[tid] = 0.f;
        __syncthreads();
        #pragma unroll
        for (int j = 0; j < 8; ++j) {
            atomicAdd(&ssum[c0 + j], sumc[j]);
            atomicAdd(&ssq [c0 + j], sqc[j]);
        }
        __syncthreads();
        atomicAdd(&g_sum[si][tid],   ssum[tid]);
        atomicAdd(&g_sqsum[si][tid], ssq[tid]);
    }
}

// ---------------- sab tile body (device) ----------------------------------
__device__ __forceinline__
void sab_body(float* smem,
              const float4* __restrict__ A, const float4* __restrict__ B,
              const int* __restrict__ nl, const int* __restrict__ bl,
              int vbid, int vgrid)
{
    float (*as)[64] = (float(*)[64])smem;            // 64*64
    float (*bs)[32] = (float(*)[32])(smem + 64*64);  // 64*32
    int* ias = (int*)(smem + 64*64 + 64*32);         // 64
    int* ibs = ias + 64;                             // 64

    const int tid = threadIdx.x;
    const int i0 = (tid >> 3) * 2;
    const int j0 = (tid & 7) * 4;
    float acc[2][4] = {{0,0,0,0},{0,0,0,0}};

    const int rowsPerBlock = R_NEI / vgrid;
    const int base = vbid * rowsPerBlock;

    for (int s = 0; s < rowsPerBlock; s += 64) {
        if (tid < 64) {
            int gr = base + s + tid;
            ias[tid] = ((gr >> 11) << 7) + nl[gr];
        } else if (tid < 128) {
            int gr = base + s + tid - 64;
            ibs[tid - 64] = ((gr >> 11) << 8) + bl[gr];
        }
        __syncthreads();
        for (int idx = tid; idx < 1024; idx += 256) {
            int row = idx >> 4, q = idx & 15;
            float4 v = A[(size_t)ias[row] * 16 + q];
            *(float4*)&as[row][q * 4] = v;
        }
        for (int idx = tid; idx < 512; idx += 256) {
            int row = idx >> 3, q = idx & 7;
            float4 v = B[(size_t)ibs[row] * 8 + q];
            *(float4*)&bs[row][q * 4] = v;
        }
        __syncthreads();
        #pragma unroll 4
        for (int k = 0; k < 64; ++k) {
            float2 a = *(const float2*)&as[k][i0];
            float4 b = *(const float4*)&bs[k][j0];
            acc[0][0] += a.x * b.x; acc[0][1] += a.x * b.y;
            acc[0][2] += a.x * b.z; acc[0][3] += a.x * b.w;
            acc[1][0] += a.y * b.x; acc[1][1] += a.y * b.y;
            acc[1][2] += a.y * b.z; acc[1][3] += a.y * b.w;
        }
        __syncthreads();
    }
    #pragma unroll
    for (int a = 0; a < 2; ++a)
        #pragma unroll
        for (int b = 0; b < 4; ++b)
            atomicAdd(&g_Sab[(i0 + a) * 32 + (j0 + b)], acc[a][b]);
}

// ---------------- fused mid kernel: P | Q | atom | sab --------------------
// blocks [0,512): P-GEMM; [512,1536): Q-GEMM; [1536,2048): atom-GEMM;
// [2048,3072): sab.
__global__ __launch_bounds__(256, 2)
void mid_kernel(const float4* __restrict__ atomF, const float4* __restrict__ bondF,
                const int* __restrict__ nl, const int* __restrict__ bl,
                const float4* __restrict__ atomW, const float4* __restrict__ neiW,
                float* __restrict__ out_atom)
{
    extern __shared__ float smem[];
    const int blk = blockIdx.x;
    if (blk < 512) {
        gemm_body<64, 2>(smem, neiW, 24, 0, atomF, g_cntA, g_P, blk);
    } else if (blk < 1536) {
        gemm_body<32, 2>(smem, neiW, 24, 16, bondF, g_cntB, g_Q, blk - 512);
    } else if (blk < 2048) {
        gemm_body<64, 1>(smem, atomW, 16, 0, atomF, nullptr, out_atom, blk - 1536);
    } else {
        sab_body(smem, atomF, bondF, nl, bl, blk - 2048, 1024);
    }
}

// ---------------- finalize: scale/shift -----------------------------------
__global__ void finalize_kernel(const float* __restrict__ atom_gamma,
                                const float* __restrict__ atom_beta,
                                const float* __restrict__ nei_W,
                                const float* __restrict__ nei_gamma,
                                const float* __restrict__ nei_beta)
{
    const int t = threadIdx.x;
    if (blockIdx.x == 256) {
        float n = (float)R_ATOM;
        float mean = g_sum[0][t] / n;
        float var  = g_sqsum[0][t] / n - mean * mean;
        float sc = atom_gamma[t] * rsqrtf(var + BN_EPS);
        g_scale[0][t] = sc;
        g_shift[0][t] = atom_beta[t] - mean * sc;
        return;
    }
    const int c = blockIdx.x;
    __shared__ float wB_s[32];
    __shared__ float red[64];
    if (t < 32) wB_s[t] = nei_W[c * 96 + 64 + t];
    __syncthreads();
    if (t < 64) {
        float v = 0.f;
        #pragma unroll
        for (int j = 0; j < 32; ++j) v += g_Sab[t * 32 + j] * wB_s[j];
        red[t] = v * nei_W[c * 96 + t];
    }
    __syncthreads();
    if (t == 0) {
        float cross = 0.f;
        #pragma unroll
        for (int j = 0; j < 64; ++j) cross += red[j];
        float n = (float)R_NEI;
        float mean = g_sum[1][c] / n;
        float var  = (g_sqsum[1][c] + 2.f * cross) / n - mean * mean;
        float sc = nei_gamma[c] * rsqrtf(var + BN_EPS);
        g_scale[1][c] = sc;
        g_shift[1][c] = nei_beta[c] - mean * sc;
    }
}

// ---------------- fused output kernel: nei_out | atom norm ----------------
// blocks [0,1024): nei_out (batch, quarter); [1024,1088): atom normalize.
__global__ __launch_bounds__(512, 2)
void out_kernel(const int* __restrict__ nl, const int* __restrict__ bl,
                float* __restrict__ out_nei, float4* __restrict__ atom_data)
{
    extern __shared__ float4 sm4[];
    const int tid = threadIdx.x;
    const int blk = blockIdx.x;

    if (blk >= 1024) {
        // atom normalize + leaky in place
        const float4* sc4 = (const float4*)g_scale[0];
        const float4* sh4 = (const float4*)g_shift[0];
        const long long n4 = ATOM_OUT_ELEMS / 4;
        long long i = (long long)(blk - 1024) * 512 + tid;
        const long long stride = 64LL * 512;
        for (; i < n4; i += stride) {
            float4 v = atom_data[i];
            int cq = (int)(i & 63);
            float4 s = sc4[cq];
            float4 h = sh4[cq];
            v.x = v.x * s.x + h.x;  v.y = v.y * s.y + h.y;
            v.z = v.z * s.z + h.z;  v.w = v.w * s.w + h.w;
            v.x = fmaxf(v.x, SLOPE * v.x);
            v.y = fmaxf(v.y, SLOPE * v.y);
            v.z = fmaxf(v.z, SLOPE * v.z);
            v.w = fmaxf(v.w, SLOPE * v.w);
            atom_data[i] = v;
        }
        return;
    }

    float4* ps = sm4;                     // 128*16
    float4* qs = sm4 + 128*16;            // 256*16
    int*    sidx = (int*)(qs + 256*16);   // 2048

    const int b    = blk >> 2;
    const int qt   = blk & 3;
    const int lane = tid & 31;
    const int warp = tid >> 5;
    const int c16  = lane & 15;

    const float4* P4 = (const float4*)g_P;
    const float4* Q4 = (const float4*)g_Q;

    for (int i = tid; i < 128*16; i += 512) {
        int a = i >> 4, q = i & 15;
        ps[i] = P4[(size_t)(b*128 + a)*64 + qt*16 + q];
    }
    for (int i = tid; i < 256*16; i += 512) {
        int bd = i >> 4, q = i & 15;
        qs[i] = Q4[(size_t)(b*256 + bd)*64 + qt*16 + q];
    }
    for (int i = tid; i < 2048; i += 512) {
        int r = b*2048 + i;
        sidx[i] = nl[r] | (bl[r] << 8);
    }
    float4 s = ((const float4*)g_scale[1])[qt*16 + c16];
    float4 h = ((const float4*)g_shift[1])[qt*16 + c16];
    __syncthreads();

    for (int rp = warp; rp < 1024; rp += 16) {
        int row = rp * 2 + (lane >> 4);
        int pk = sidx[row];
        float4 p = ps[(pk & 255) * 16 + c16];
        float4 q = qs[(pk >> 8) * 16 + c16];
        float4 v;
        v.x = (p.x + q.x) * s.x + h.x;
        v.y = (p.y + q.y) * s.y + h.y;
        v.z = (p.z + q.z) * s.z + h.z;
        v.w = (p.w + q.w) * s.w + h.w;
        v.x = fmaxf(v.x, SLOPE * v.x);
        v.y = fmaxf(v.y, SLOPE * v.y);
        v.z = fmaxf(v.z, SLOPE * v.z);
        v.w = fmaxf(v.w, SLOPE * v.w);
        *(float4*)&out_nei[(size_t)(b*2048 + row)*256 + qt*64 + c16*4] = v;
    }
}

// ---------------- launcher ------------------------------------------------
extern "C" void kernel_launch(void* const* d_in, const int* in_sizes, int n_in,
                              void* d_out, int out_size) {
    const float* atom_features = (const float*)d_in[0];
    const float* bond_features = (const float*)d_in[1];
    const int*   atom_nl       = (const int*)  d_in[2];
    const int*   bond_nl       = (const int*)  d_in[3];
    const float* atom_W        = (const float*)d_in[4];
    const float* atom_gamma    = (const float*)d_in[6];
    const float* atom_beta     = (const float*)d_in[7];
    const float* nei_W         = (const float*)d_in[8];
    const float* nei_gamma     = (const float*)d_in[10];
    const float* nei_beta      = (const float*)d_in[11];

    float* out_atom = (float*)d_out;
    float* out_nei  = (float*)d_out + ATOM_OUT_ELEMS;

    const int smemMid = (64*FPC + 64*64 + 64 + 2*FPC) * (int)sizeof(float); // 84224
    const int smemOut = (128*16 + 256*16) * 16 + 2048 * 4;                  // 106496
    cudaFuncSetAttribute((const void*)mid_kernel,
                         cudaFuncAttributeMaxDynamicSharedMemorySize, smemMid);
    cudaFuncSetAttribute((const void*)out_kernel,
                         cudaFuncAttributeMaxDynamicSharedMemorySize, smemOut);

    // 1) per-batch count histograms + zero accumulators
    prelude_kernel<<<BATCH + 1, 256>>>(atom_nl, bond_nl);

    // 2) fused: P-GEMM | Q-GEMM | atom-GEMM | sab  (block-level concurrency)
    mid_kernel<<<3072, 256, smemMid>>>(
        (const float4*)atom_features, (const float4*)bond_features,
        atom_nl, bond_nl,
        (const float4*)atom_W, (const float4*)nei_W, out_atom);

    // 3) scale/shift for both branches
    finalize_kernel<<<257, 256>>>(atom_gamma, atom_beta,
                                  nei_W, nei_gamma, nei_beta);

    // 4) fused: nei output | atom normalize
    out_kernel<<<1088, 512, smemOut>>>(atom_nl, bond_nl, out_nei,
                                       (float4*)out_atom);
}

// round 8
// speedup vs baseline: 1.2329x; 1.2329x over previous
#include <cuda_runtime.h>
#include <cstdint>
#include <cstddef>

#define BATCH 256
#define ANUM  128
#define NBNUM 256
#define DNUM  16
#define FA    64
#define FB    32
#define FPC   256
#define R_NEI  (BATCH*ANUM*DNUM)   // 524288
#define R_ATOM (BATCH*ANUM)        // 32768
#define R_BOND (BATCH*NBNUM)       // 65536
#define ATOM_OUT_ELEMS ((long long)R_ATOM*FPC)
#define NEI_OUT_ELEMS  ((long long)R_NEI*FPC)
#define BN_EPS 1e-6f
#define SLOPE  0.01f

// ---------------- device scratch ----------------
__device__ float g_P[(size_t)R_ATOM * FPC];   // 33.5 MB
__device__ float g_Q[(size_t)R_BOND * FPC];   // 67 MB
__device__ float g_Sx[64*64];                 // atom 2nd moment
__device__ float g_mx[64];                    // atom 1st moment
__device__ float g_sum1[FPC];                 // nei sum t
__device__ float g_sq1[FPC];                  // nei sum t^2
__device__ float g_scale[2][FPC];
__device__ float g_shift[2][FPC];

// ---------------- packed f32x2 helpers ----------------
__device__ __forceinline__ unsigned long long pack2(float lo, float hi) {
    unsigned long long r;
    asm("mov.b64 %0, {%1,%2};" : "=l"(r) : "f"(lo), "f"(hi));
    return r;
}
__device__ __forceinline__ void fma2(unsigned long long& d,
                                     unsigned long long a,
                                     unsigned long long b) {
    asm("fma.rn.f32x2 %0, %1, %2, %0;" : "+l"(d) : "l"(a), "l"(b));
}
__device__ __forceinline__ float2 unpack2(unsigned long long v) {
    float2 r;
    asm("mov.b64 {%0,%1}, %2;" : "=f"(r.x), "=f"(r.y) : "l"(v));
    return r;
}

// ---------------- zero scratch ----------------
__global__ void zero_kernel() {
    const int tid = threadIdx.x;
    for (int i = tid; i < 64*64; i += 256) g_Sx[i] = 0.f;
    if (tid < 64) g_mx[tid] = 0.f;
    g_sum1[tid] = 0.f;
    g_sq1[tid]  = 0.f;
}

// ---------------- GEMM tile body: out[r][c] = W[c].X[r] -------------------
// NORM: apply g_scale[0]/g_shift[0] + leaky, streaming store.
template<int K, bool NORM>
__device__ __forceinline__
void gemm_body(float* smem,
               const float4* __restrict__ Wg, int wldq, int woffq,
               const float4* __restrict__ X,
               float* __restrict__ out, int tile)
{
    constexpr int KQ = K / 4;
    float* ws = smem;               // K*256
    float* xs = smem + K * FPC;     // K*64

    const int tid = threadIdx.x;
    const int r0 = (tid >> 5) * 8;
    const int c0 = (tid & 31) * 8;

    for (int idx = tid; idx < FPC * KQ; idx += 256) {
        int q = idx >> 8;
        int c = idx & 255;
        float4 v = Wg[(size_t)c * wldq + woffq + q];
        ws[(4*q+0)*FPC + c] = v.x;
        ws[(4*q+1)*FPC + c] = v.y;
        ws[(4*q+2)*FPC + c] = v.z;
        ws[(4*q+3)*FPC + c] = v.w;
    }
    for (int idx = tid; idx < 64 * KQ; idx += 256) {
        int lr = idx & 63;
        int q  = idx >> 6;
        float4 v = X[(size_t)(tile * 64 + lr) * KQ + q];
        xs[(4*q+0)*64 + lr] = v.x;
        xs[(4*q+1)*64 + lr] = v.y;
        xs[(4*q+2)*64 + lr] = v.z;
        xs[(4*q+3)*64 + lr] = v.w;
    }
    float scv[8], shv[8];
    if (NORM) {
        #pragma unroll
        for (int j = 0; j < 8; ++j) {
            scv[j] = g_scale[0][c0 + j];
            shv[j] = g_shift[0][c0 + j];
        }
    }
    __syncthreads();

    unsigned long long acc[8][4];
    #pragma unroll
    for (int i = 0; i < 8; ++i)
        #pragma unroll
        for (int j = 0; j < 4; ++j) acc[i][j] = 0ull;

    #pragma unroll 2
    for (int k = 0; k < K; ++k) {
        const float4 xa = *(const float4*)&xs[k*64 + r0];
        const float4 xb = *(const float4*)&xs[k*64 + r0 + 4];
        const ulonglong2 w0 = *(const ulonglong2*)&ws[k*FPC + c0];
        const ulonglong2 w1 = *(const ulonglong2*)&ws[k*FPC + c0 + 4];
        unsigned long long xp[8];
        xp[0] = pack2(xa.x, xa.x); xp[1] = pack2(xa.y, xa.y);
        xp[2] = pack2(xa.z, xa.z); xp[3] = pack2(xa.w, xa.w);
        xp[4] = pack2(xb.x, xb.x); xp[5] = pack2(xb.y, xb.y);
        xp[6] = pack2(xb.z, xb.z); xp[7] = pack2(xb.w, xb.w);
        #pragma unroll
        for (int i = 0; i < 8; ++i) {
            fma2(acc[i][0], xp[i], w0.x);
            fma2(acc[i][1], xp[i], w0.y);
            fma2(acc[i][2], xp[i], w1.x);
            fma2(acc[i][3], xp[i], w1.y);
        }
    }

    #pragma unroll
    for (int i = 0; i < 8; ++i) {
        float y[8];
        #pragma unroll
        for (int j = 0; j < 4; ++j) {
            float2 p = unpack2(acc[i][j]);
            y[2*j]   = p.x;
            y[2*j+1] = p.y;
        }
        size_t row = (size_t)tile * 64 + r0 + i;
        float4* o = (float4*)&out[row * FPC + c0];
        if (NORM) {
            #pragma unroll
            for (int j = 0; j < 8; ++j) {
                y[j] = y[j] * scv[j] + shv[j];
                y[j] = fmaxf(y[j], SLOPE * y[j]);
            }
            __stcs(o,     make_float4(y[0], y[1], y[2], y[3]));
            __stcs(o + 1, make_float4(y[4], y[5], y[6], y[7]));
        } else {
            o[0] = make_float4(y[0], y[1], y[2], y[3]);
            o[1] = make_float4(y[4], y[5], y[6], y[7]);
        }
    }
}

// ---------------- Sx body: Sx += X_blk^T X_blk, mx += sum(X_blk) ----------
__device__ __forceinline__
void sx_body(float* smem, const float4* __restrict__ X, int vbid)
{
    float (*xs)[64] = (float(*)[64])smem;   // 32 x 64
    const int tid = threadIdx.x;
    const int i0 = (tid >> 4) * 4;
    const int j0 = (tid & 15) * 4;

    float acc[4][4];
    #pragma unroll
    for (int a = 0; a < 4; ++a)
        #pragma unroll
        for (int b = 0; b < 4; ++b) acc[a][b] = 0.f;
    float mp[4] = {0.f, 0.f, 0.f, 0.f};

    const int base = vbid * 128;
    for (int s = 0; s < 128; s += 32) {
        for (int idx = tid; idx < 512; idx += 256) {
            int row = idx >> 4, q = idx & 15;
            float4 v = X[(size_t)(base + s + row) * 16 + q];
            *(float4*)&xs[row][q * 4] = v;
        }
        __syncthreads();
        for (int k = 0; k < 32; ++k) {
            float xi[4], xj[4];
            #pragma unroll
            for (int a = 0; a < 4; ++a) { xi[a] = xs[k][i0 + a]; xj[a] = xs[k][j0 + a]; }
            #pragma unroll
            for (int a = 0; a < 4; ++a)
                #pragma unroll
                for (int b = 0; b < 4; ++b) acc[a][b] += xi[a] * xj[b];
            if ((tid >> 4) == 0) {
                #pragma unroll
                for (int b = 0; b < 4; ++b) mp[b] += xj[b];
            }
        }
        __syncthreads();
    }
    #pragma unroll
    for (int a = 0; a < 4; ++a)
        #pragma unroll
        for (int b = 0; b < 4; ++b)
            atomicAdd(&g_Sx[(i0 + a) * 64 + (j0 + b)], acc[a][b]);
    if ((tid >> 4) == 0) {
        #pragma unroll
        for (int b = 0; b < 4; ++b) atomicAdd(&g_mx[j0 + b], mp[b]);
    }
}

// ---------------- mid: P-GEMM | Q-GEMM | Sx --------------------------------
// blocks [0,512): P; [512,1536): Q; [1536,1792): Sx.
__global__ __launch_bounds__(256, 2)
void mid_kernel(const float4* __restrict__ atomF, const float4* __restrict__ bondF,
                const float4* __restrict__ neiW)
{
    extern __shared__ float smem[];
    const int blk = blockIdx.x;
    if (blk < 512) {
        gemm_body<64, false>(smem, neiW, 24, 0, atomF, g_P, blk);
    } else if (blk < 1536) {
        gemm_body<32, false>(smem, neiW, 24, 16, bondF, g_Q, blk - 512);
    } else {
        sx_body(smem, atomF, blk - 1536);
    }
}

// ---------------- finalize atom scale (analytic via Sx) -------------------
__global__ void finalize_atom_kernel(const float* __restrict__ atom_W,
                                     const float* __restrict__ atom_gamma,
                                     const float* __restrict__ atom_beta)
{
    const int c = blockIdx.x;
    const int t = threadIdx.x;    // 64 threads
    __shared__ float w[64];
    __shared__ float red[64], red2[64];
    w[t] = atom_W[c * 64 + t];
    __syncthreads();
    float v = 0.f;
    #pragma unroll 8
    for (int j = 0; j < 64; ++j) v += g_Sx[t * 64 + j] * w[j];
    red[t]  = w[t] * v;
    red2[t] = w[t] * g_mx[t];
    __syncthreads();
    for (int s = 32; s > 0; s >>= 1) {
        if (t < s) { red[t] += red[t + s]; red2[t] += red2[t + s]; }
        __syncthreads();
    }
    if (t == 0) {
        float n = (float)R_ATOM;
        float mean = red2[0] / n;
        float var  = red[0] / n - mean * mean;
        float sc = atom_gamma[c] * rsqrtf(var + BN_EPS);
        g_scale[0][c] = sc;
        g_shift[0][c] = atom_beta[c] - mean * sc;
    }
}

// ---------------- stats body: per (batch,quarter) sum/sq of t=P[a]+Q[b] ---
__device__ __forceinline__
void stats_body(float4* sm4, const int* __restrict__ nl, const int* __restrict__ bl,
                int b, int qt)
{
    float4* ps = sm4;                     // 128*16 f4 (32KB)
    float4* qs = sm4 + 128*16;            // 256*16 f4 (64KB)
    int*    sidx = (int*)(qs + 256*16);   // 2048 ints (8KB)
    float*  red  = (float*)(sidx + 2048); // 128 floats

    const int tid  = threadIdx.x;
    const int lane = tid & 31;
    const int warp = tid >> 5;            // 0..7
    const int c16  = lane & 15;

    const float4* P4 = (const float4*)g_P;
    const float4* Q4 = (const float4*)g_Q;

    for (int i = tid; i < 128*16; i += 256) {
        int a = i >> 4, q = i & 15;
        ps[i] = P4[(size_t)(b*128 + a)*64 + qt*16 + q];
    }
    for (int i = tid; i < 256*16; i += 256) {
        int bd = i >> 4, q = i & 15;
        qs[i] = Q4[(size_t)(b*256 + bd)*64 + qt*16 + q];
    }
    for (int i = tid; i < 2048; i += 256) {
        int r = b*2048 + i;
        sidx[i] = nl[r] | (bl[r] << 8);
    }
    if (tid < 128) red[tid] = 0.f;
    __syncthreads();

    float s1[4] = {0,0,0,0};
    float s2[4] = {0,0,0,0};
    for (int rp = warp; rp < 1024; rp += 8) {
        int row = rp * 2 + (lane >> 4);
        int pk = sidx[row];
        float4 p = ps[(pk & 255) * 16 + c16];
        float4 q = qs[(pk >> 8) * 16 + c16];
        float t0 = p.x + q.x, t1 = p.y + q.y, t2 = p.z + q.z, t3 = p.w + q.w;
        s1[0] += t0; s1[1] += t1; s1[2] += t2; s1[3] += t3;
        s2[0] += t0*t0; s2[1] += t1*t1; s2[2] += t2*t2; s2[3] += t3*t3;
    }
    __syncthreads();
    #pragma unroll
    for (int j = 0; j < 4; ++j) {
        atomicAdd(&red[c16*4 + j],      s1[j]);
        atomicAdd(&red[64 + c16*4 + j], s2[j]);
    }
    __syncthreads();
    if (tid < 64) {
        atomicAdd(&g_sum1[qt*64 + tid], red[tid]);
        atomicAdd(&g_sq1 [qt*64 + tid], red[64 + tid]);
    }
}

// ---------------- fused: nei stats | atom-GEMM with fused normalize -------
// blocks [0,1024): stats (batch, quarter); [1024,1536): atom GEMM+norm.
__global__ __launch_bounds__(256, 2)
void statsgemm_kernel(const int* __restrict__ nl, const int* __restrict__ bl,
                      const float4* __restrict__ atomF,
                      const float4* __restrict__ atomW,
                      float* __restrict__ out_atom)
{
    extern __shared__ float smem[];
    const int blk = blockIdx.x;
    if (blk < 1024) {
        stats_body((float4*)smem, nl, bl, blk >> 2, blk & 3);
    } else {
        gemm_body<64, true>(smem, atomW, 16, 0, atomF, out_atom, blk - 1024);
    }
}

// ---------------- finalize nei scale ---------------------------------------
__global__ void finalize_nei_kernel(const float* __restrict__ nei_gamma,
                                    const float* __restrict__ nei_beta)
{
    const int c = threadIdx.x;
    float n = (float)R_NEI;
    float mean = g_sum1[c] / n;
    float var  = g_sq1[c] / n - mean * mean;
    float sc = nei_gamma[c] * rsqrtf(var + BN_EPS);
    g_scale[1][c] = sc;
    g_shift[1][c] = nei_beta[c] - mean * sc;
}

// ---------------- nei output: smem-cached P/Q channel-quarters ------------
__global__ __launch_bounds__(512, 2)
void nei_out_kernel(const int* __restrict__ nl, const int* __restrict__ bl,
                    float* __restrict__ out_nei)
{
    extern __shared__ float4 sm4[];
    float4* ps = sm4;                     // 128*16
    float4* qs = sm4 + 128*16;            // 256*16
    int*    sidx = (int*)(qs + 256*16);   // 2048

    const int tid  = threadIdx.x;
    const int blk  = blockIdx.x;
    const int b    = blk >> 2;
    const int qt   = blk & 3;
    const int lane = tid & 31;
    const int warp = tid >> 5;
    const int c16  = lane & 15;

    const float4* P4 = (const float4*)g_P;
    const float4* Q4 = (const float4*)g_Q;

    for (int i = tid; i < 128*16; i += 512) {
        int a = i >> 4, q = i & 15;
        ps[i] = P4[(size_t)(b*128 + a)*64 + qt*16 + q];
    }
    for (int i = tid; i < 256*16; i += 512) {
        int bd = i >> 4, q = i & 15;
        qs[i] = Q4[(size_t)(b*256 + bd)*64 + qt*16 + q];
    }
    for (int i = tid; i < 2048; i += 512) {
        int r = b*2048 + i;
        sidx[i] = nl[r] | (bl[r] << 8);
    }
    float4 s = ((const float4*)g_scale[1])[qt*16 + c16];
    float4 h = ((const float4*)g_shift[1])[qt*16 + c16];
    __syncthreads();

    for (int rp = warp; rp < 1024; rp += 16) {
        int row = rp * 2 + (lane >> 4);
        int pk = sidx[row];
        float4 p = ps[(pk & 255) * 16 + c16];
        float4 q = qs[(pk >> 8) * 16 + c16];
        float4 v;
        v.x = (p.x + q.x) * s.x + h.x;
        v.y = (p.y + q.y) * s.y + h.y;
        v.z = (p.z + q.z) * s.z + h.z;
        v.w = (p.w + q.w) * s.w + h.w;
        v.x = fmaxf(v.x, SLOPE * v.x);
        v.y = fmaxf(v.y, SLOPE * v.y);
        v.z = fmaxf(v.z, SLOPE * v.z);
        v.w = fmaxf(v.w, SLOPE * v.w);
        __stcs((float4*)&out_nei[(size_t)(b*2048 + row)*256 + qt*64 + c16*4], v);
    }
}

// ---------------- launcher ------------------------------------------------
extern "C" void kernel_launch(void* const* d_in, const int* in_sizes, int n_in,
                              void* d_out, int out_size) {
    const float* atom_features = (const float*)d_in[0];
    const float* bond_features = (const float*)d_in[1];
    const int*   atom_nl       = (const int*)  d_in[2];
    const int*   bond_nl       = (const int*)  d_in[3];
    const float* atom_W        = (const float*)d_in[4];
    const float* atom_gamma    = (const float*)d_in[6];
    const float* atom_beta     = (const float*)d_in[7];
    const float* nei_W         = (const float*)d_in[8];
    const float* nei_gamma     = (const float*)d_in[10];
    const float* nei_beta      = (const float*)d_in[11];

    float* out_atom = (float*)d_out;
    float* out_nei  = (float*)d_out + ATOM_OUT_ELEMS;

    const int smemMid = (64*FPC + 64*64) * (int)sizeof(float);            // 81920
    const int smemSG  = (128*16 + 256*16) * 16 + 2048 * 4 + 128 * 4;      // 107008
    const int smemOut = (128*16 + 256*16) * 16 + 2048 * 4;                // 106496
    cudaFuncSetAttribute((const void*)mid_kernel,
                         cudaFuncAttributeMaxDynamicSharedMemorySize, smemMid);
    cudaFuncSetAttribute((const void*)statsgemm_kernel,
                         cudaFuncAttributeMaxDynamicSharedMemorySize, smemSG);
    cudaFuncSetAttribute((const void*)nei_out_kernel,
                         cudaFuncAttributeMaxDynamicSharedMemorySize, smemOut);

    // 1) zero accumulators
    zero_kernel<<<1, 256>>>();

    // 2) P-GEMM | Q-GEMM | atom feature moments (Sx, mx)
    mid_kernel<<<1792, 256, smemMid>>>(
        (const float4*)atom_features, (const float4*)bond_features,
        (const float4*)nei_W);

    // 3) atom scale/shift (analytic quadratic form)
    finalize_atom_kernel<<<256, 64>>>(atom_W, atom_gamma, atom_beta);

    // 4) nei stats (smem-staged t moments) | atom GEMM with fused norm+leaky
    statsgemm_kernel<<<1536, 256, smemSG>>>(
        atom_nl, bond_nl, (const float4*)atom_features,
        (const float4*)atom_W, out_atom);

    // 5) nei scale/shift
    finalize_nei_kernel<<<1, 256>>>(nei_gamma, nei_beta);

    // 6) nei output: fused gather + normalize + leaky, streaming stores
    nei_out_kernel<<<1024, 512, smemOut>>>(atom_nl, bond_nl, out_nei);
}

// round 10
// speedup vs baseline: 1.4135x; 1.1465x over previous
#include <cuda_runtime.h>
#include <cstdint>
#include <cstddef>

#define BATCH 256
#define ANUM  128
#define NBNUM 256
#define DNUM  16
#define FA    64
#define FB    32
#define FPC   256
#define R_NEI  (BATCH*ANUM*DNUM)   // 524288
#define R_ATOM (BATCH*ANUM)        // 32768
#define R_BOND (BATCH*NBNUM)       // 65536
#define ATOM_OUT_ELEMS ((long long)R_ATOM*FPC)
#define NEI_OUT_ELEMS  ((long long)R_NEI*FPC)
#define BN_EPS 1e-6f
#define SLOPE  0.01f

// ---------------- device scratch ----------------
__device__ float g_P[(size_t)R_ATOM * FPC];   // 33.5 MB
__device__ float g_Q[(size_t)R_BOND * FPC];   // 67 MB
__device__ float g_cntA[R_ATOM];
__device__ float g_cntB[R_BOND];
__device__ int   g_csr[R_NEI];                // per-batch CSR: bond idx lists
__device__ int   g_offs[R_ATOM];              // per-batch CSR offsets
__device__ float g_Sx[64*64];                 // atom 2nd moment
__device__ float g_mx[64];                    // atom 1st moment
__device__ float g_Sab[64*32];                // raw-feature cross moment
__device__ float g_sum1[FPC];                 // nei sum t  (weighted epilogues)
__device__ float g_sq1[FPC];                  // nei sum t^2 (minus cross)
__device__ float g_scale[2][FPC];
__device__ float g_shift[2][FPC];

// Shared-memory budgets (floats), mirroring the body layouts EXACTLY.
#define SMEM_GEMM_F   (64*FPC + 64*64 + 64 + 2*FPC)          // 21056
#define SMEM_CROSS_F  (128*64 + 8*2048 + 128 + 128)          // 24832
#define SMEM_MID_F    (SMEM_CROSS_F > SMEM_GEMM_F ? SMEM_CROSS_F : SMEM_GEMM_F)

// ---------------- packed f32x2 helpers ----------------
__device__ __forceinline__ unsigned long long pack2(float lo, float hi) {
    unsigned long long r;
    asm("mov.b64 %0, {%1,%2};" : "=l"(r) : "f"(lo), "f"(hi));
    return r;
}
__device__ __forceinline__ void fma2(unsigned long long& d,
                                     unsigned long long a,
                                     unsigned long long b) {
    asm("fma.rn.f32x2 %0, %1, %2, %0;" : "+l"(d) : "l"(a), "l"(b));
}
__device__ __forceinline__ float2 unpack2(unsigned long long v) {
    float2 r;
    asm("mov.b64 {%0,%1}, %2;" : "=f"(r.x), "=f"(r.y) : "l"(v));
    return r;
}

// ---------------- zero scratch ----------------
__global__ void zero_kernel() {
    const int tid = threadIdx.x;
    for (int i = tid; i < 64*64; i += 256) g_Sx[i] = 0.f;
    for (int i = tid; i < 64*32; i += 256) g_Sab[i] = 0.f;
    if (tid < 64) g_mx[tid] = 0.f;
    g_sum1[tid] = 0.f;
    g_sq1[tid]  = 0.f;
}

// ---------------- Sx body: Sx += X_blk^T X_blk, mx += sum(X_blk) ----------
__device__ __forceinline__
void sx_body(float* smem, const float4* __restrict__ X, int vbid)
{
    float (*xs)[64] = (float(*)[64])smem;   // 32 x 64
    const int tid = threadIdx.x;
    const int i0 = (tid >> 4) * 4;
    const int j0 = (tid & 15) * 4;

    float acc[4][4];
    #pragma unroll
    for (int a = 0; a < 4; ++a)
        #pragma unroll
        for (int b = 0; b < 4; ++b) acc[a][b] = 0.f;
    float mp[4] = {0.f, 0.f, 0.f, 0.f};

    const int base = vbid * 128;
    for (int s = 0; s < 128; s += 32) {
        for (int idx = tid; idx < 512; idx += 256) {
            int row = idx >> 4, q = idx & 15;
            float4 v = X[(size_t)(base + s + row) * 16 + q];
            *(float4*)&xs[row][q * 4] = v;
        }
        __syncthreads();
        for (int k = 0; k < 32; ++k) {
            float xi[4], xj[4];
            #pragma unroll
            for (int a = 0; a < 4; ++a) { xi[a] = xs[k][i0 + a]; xj[a] = xs[k][j0 + a]; }
            #pragma unroll
            for (int a = 0; a < 4; ++a)
                #pragma unroll
                for (int b = 0; b < 4; ++b) acc[a][b] += xi[a] * xj[b];
            if ((tid >> 4) == 0) {
                #pragma unroll
                for (int b = 0; b < 4; ++b) mp[b] += xj[b];
            }
        }
        __syncthreads();
    }
    #pragma unroll
    for (int a = 0; a < 4; ++a)
        #pragma unroll
        for (int b = 0; b < 4; ++b)
            atomicAdd(&g_Sx[(i0 + a) * 64 + (j0 + b)], acc[a][b]);
    if ((tid >> 4) == 0) {
        #pragma unroll
        for (int b = 0; b < 4; ++b) atomicAdd(&g_mx[j0 + b], mp[b]);
    }
}

// ---------------- prelude: per-batch counts + CSR | Sx --------------------
// blocks [0,256): counts + CSR for batch blk; [256,512): Sx.
__global__ __launch_bounds__(256)
void prelude_kernel(const int* __restrict__ nl, const int* __restrict__ bl,
                    const float4* __restrict__ atomF)
{
    __shared__ int hA[ANUM];
    __shared__ int hB[NBNUM];
    __shared__ int offs[ANUM];
    __shared__ int total;
    extern __shared__ float dsm[];

    const int blk = blockIdx.x;
    const int tid = threadIdx.x;

    if (blk >= 256) { sx_body(dsm, atomF, blk - 256); return; }

    const int b = blk;
    if (tid < ANUM) hA[tid] = 0;
    hB[tid] = 0;
    if (tid == 0) total = 0;
    __syncthreads();
    const int base = b * 2048;
    for (int i = tid; i < 2048; i += 256) {
        atomicAdd(&hA[nl[base + i]], 1);
        atomicAdd(&hB[bl[base + i]], 1);
    }
    __syncthreads();
    if (tid < ANUM) {
        int c = hA[tid];
        int o = atomicAdd(&total, c);
        offs[tid] = o;
        g_offs[b * ANUM + tid] = o;
        g_cntA[b * ANUM + tid] = (float)c;
    }
    g_cntB[b * NBNUM + tid] = (float)hB[tid];
    __syncthreads();
    if (tid < ANUM) hA[tid] = 0;   // reuse as cursor
    __syncthreads();
    for (int i = tid; i < 2048; i += 256) {
        int a = nl[base + i];
        int slot = offs[a] + atomicAdd(&hA[a], 1);
        g_csr[base + slot] = bl[base + i];
    }
}

// ---------------- GEMM tile body -------------------------------------------
// SMODE: 0 = none, 1 = fused normalize+leaky (uses g_scale[0]),
//        2 = cnt-weighted stats -> g_sum1/g_sq1
template<int K, int SMODE>
__device__ __forceinline__
void gemm_body(float* smem,
               const float4* __restrict__ Wg, int wldq, int woffq,
               const float4* __restrict__ X, const float* __restrict__ cnt,
               float* __restrict__ out, int tile)
{
    constexpr int KQ = K / 4;
    float* ws = smem;               // K*256
    float* xs = smem + K * FPC;     // K*64
    float* cw   = xs + K * 64;      // 64
    float* ssum = cw + 64;          // 256
    float* ssq  = ssum + FPC;       // 256

    const int tid = threadIdx.x;
    const int r0 = (tid >> 5) * 8;
    const int c0 = (tid & 31) * 8;

    for (int idx = tid; idx < FPC * KQ; idx += 256) {
        int q = idx >> 8;
        int c = idx & 255;
        float4 v = Wg[(size_t)c * wldq + woffq + q];
        ws[(4*q+0)*FPC + c] = v.x;
        ws[(4*q+1)*FPC + c] = v.y;
        ws[(4*q+2)*FPC + c] = v.z;
        ws[(4*q+3)*FPC + c] = v.w;
    }
    for (int idx = tid; idx < 64 * KQ; idx += 256) {
        int lr = idx & 63;
        int q  = idx >> 6;
        float4 v = X[(size_t)(tile * 64 + lr) * KQ + q];
        xs[(4*q+0)*64 + lr] = v.x;
        xs[(4*q+1)*64 + lr] = v.y;
        xs[(4*q+2)*64 + lr] = v.z;
        xs[(4*q+3)*64 + lr] = v.w;
    }
    if (SMODE == 2 && tid < 64) cw[tid] = cnt[tile * 64 + tid];
    float scv[8], shv[8];
    if (SMODE == 1) {
        #pragma unroll
        for (int j = 0; j < 8; ++j) {
            scv[j] = g_scale[0][c0 + j];
            shv[j] = g_shift[0][c0 + j];
        }
    }
    __syncthreads();

    unsigned long long acc[8][4];
    #pragma unroll
    for (int i = 0; i < 8; ++i)
        #pragma unroll
        for (int j = 0; j < 4; ++j) acc[i][j] = 0ull;

    #pragma unroll 2
    for (int k = 0; k < K; ++k) {
        const float4 xa = *(const float4*)&xs[k*64 + r0];
        const float4 xb = *(const float4*)&xs[k*64 + r0 + 4];
        const ulonglong2 w0 = *(const ulonglong2*)&ws[k*FPC + c0];
        const ulonglong2 w1 = *(const ulonglong2*)&ws[k*FPC + c0 + 4];
        unsigned long long xp[8];
        xp[0] = pack2(xa.x, xa.x); xp[1] = pack2(xa.y, xa.y);
        xp[2] = pack2(xa.z, xa.z); xp[3] = pack2(xa.w, xa.w);
        xp[4] = pack2(xb.x, xb.x); xp[5] = pack2(xb.y, xb.y);
        xp[6] = pack2(xb.z, xb.z); xp[7] = pack2(xb.w, xb.w);
        #pragma unroll
        for (int i = 0; i < 8; ++i) {
            fma2(acc[i][0], xp[i], w0.x);
            fma2(acc[i][1], xp[i], w0.y);
            fma2(acc[i][2], xp[i], w1.x);
            fma2(acc[i][3], xp[i], w1.y);
        }
    }

    float sumc[8], sqc[8];
    if (SMODE == 2) {
        #pragma unroll
        for (int j = 0; j < 8; ++j) { sumc[j] = 0.f; sqc[j] = 0.f; }
    }

    #pragma unroll
    for (int i = 0; i < 8; ++i) {
        float y[8];
        #pragma unroll
        for (int j = 0; j < 4; ++j) {
            float2 p = unpack2(acc[i][j]);
            y[2*j]   = p.x;
            y[2*j+1] = p.y;
        }
        size_t row = (size_t)tile * 64 + r0 + i;
        float4* o = (float4*)&out[row * FPC + c0];
        if (SMODE == 1) {
            #pragma unroll
            for (int j = 0; j < 8; ++j) {
                y[j] = y[j] * scv[j] + shv[j];
                y[j] = fmaxf(y[j], SLOPE * y[j]);
            }
            __stcs(o,     make_float4(y[0], y[1], y[2], y[3]));
            __stcs(o + 1, make_float4(y[4], y[5], y[6], y[7]));
        } else {
            if (SMODE == 2) {
                float c = cw[r0 + i];
                #pragma unroll
                for (int j = 0; j < 8; ++j) { sumc[j] += c*y[j]; sqc[j] += c*y[j]*y[j]; }
            }
            o[0] = make_float4(y[0], y[1], y[2], y[3]);
            o[1] = make_float4(y[4], y[5], y[6], y[7]);
        }
    }

    if (SMODE == 2) {
        __syncthreads();
        ssum[tid] = 0.f; ssq[tid] = 0.f;
        __syncthreads();
        #pragma unroll
        for (int j = 0; j < 8; ++j) {
            atomicAdd(&ssum[c0 + j], sumc[j]);
            atomicAdd(&ssq [c0 + j], sqc[j]);
        }
        __syncthreads();
        atomicAdd(&g_sum1[tid], ssum[tid]);
        atomicAdd(&g_sq1[tid],  ssq[tid]);
    }
}

// ---------------- crossdot body: Sab += A_b^T G_b via CSR ------------------
__device__ __forceinline__
void crossdot_body(float* smem, const float4* __restrict__ atomF,
                   const float* __restrict__ bondF, int b)
{
    float (*as)[64] = (float(*)[64])smem;        // 128*64 floats
    float* partial  = smem + 128*64;             // 8*2048 floats
    int*   soffs    = (int*)(partial + 8*2048);  // 128
    int*   scnt     = soffs + 128;               // 128
    // total = SMEM_CROSS_F floats (checked against launch budget)

    const int tid  = threadIdx.x;
    const int lane = tid & 31;
    const int warp = tid >> 5;

    for (int idx = tid; idx < 128*16; idx += 256) {
        int row = idx >> 4, q = idx & 15;
        float4 v = atomF[(size_t)(b*128 + row) * 16 + q];
        *(float4*)&as[row][q*4] = v;
    }
    if (tid < 128) {
        soffs[tid] = g_offs[b * ANUM + tid];
        scnt[tid]  = (int)g_cntA[b * ANUM + tid];
    }
    __syncthreads();

    float acc[64];
    #pragma unroll
    for (int i = 0; i < 64; ++i) acc[i] = 0.f;

    const float* B = bondF + (size_t)b * NBNUM * FB;
    const int* csr = g_csr + (size_t)b * 2048;

    for (int a = warp; a < 128; a += 8) {
        const int off = soffs[a];
        const int cn  = scnt[a];
        float g = 0.f;
        for (int j = 0; j < cn; ++j) {
            int bidx = csr[off + j];
            g += B[bidx * FB + lane];
        }
        #pragma unroll
        for (int i = 0; i < 64; ++i) acc[i] += as[a][i] * g;
    }
    #pragma unroll
    for (int i = 0; i < 64; ++i) partial[warp*2048 + i*32 + lane] = acc[i];
    __syncthreads();
    for (int e = tid; e < 2048; e += 256) {
        float s = 0.f;
        #pragma unroll
        for (int w = 0; w < 8; ++w) s += partial[w*2048 + e];
        atomicAdd(&g_Sab[e], s);   // Sab[i][j], e = i*32 + j
    }
}

// ---------------- mega mid: P | Q | atomGEMM+norm | crossdot ---------------
// blocks [0,256): crossdot (longest per-block: schedule first);
// [256,768): P; [768,1792): Q; [1792,2304): atom.
__global__ __launch_bounds__(256, 2)
void mid_kernel(const float4* __restrict__ atomF, const float4* __restrict__ bondF,
                const float4* __restrict__ atomW, const float4* __restrict__ neiW,
                float* __restrict__ out_atom)
{
    extern __shared__ float smem[];
    const int blk = blockIdx.x;
    if (blk < 256) {
        crossdot_body(smem, atomF, (const float*)bondF, blk);
    } else if (blk < 768) {
        gemm_body<64, 2>(smem, neiW, 24, 0, atomF, g_cntA, g_P, blk - 256);
    } else if (blk < 1792) {
        gemm_body<32, 2>(smem, neiW, 24, 16, bondF, g_cntB, g_Q, blk - 768);
    } else {
        gemm_body<64, 1>(smem, atomW, 16, 0, atomF, nullptr, out_atom, blk - 1792);
    }
}

// ---------------- finalize atom scale (analytic via Sx) --------------------
__global__ void finalize_atom_kernel(const float* __restrict__ atom_W,
                                     const float* __restrict__ atom_gamma,
                                     const float* __restrict__ atom_beta)
{
    const int c = blockIdx.x;
    const int t = threadIdx.x;    // 64 threads
    __shared__ float w[64];
    __shared__ float red[64], red2[64];
    w[t] = atom_W[c * 64 + t];
    __syncthreads();
    float v = 0.f;
    #pragma unroll 8
    for (int j = 0; j < 64; ++j) v += g_Sx[t * 64 + j] * w[j];
    red[t]  = w[t] * v;
    red2[t] = w[t] * g_mx[t];
    __syncthreads();
    for (int s = 32; s > 0; s >>= 1) {
        if (t < s) { red[t] += red[t + s]; red2[t] += red2[t + s]; }
        __syncthreads();
    }
    if (t == 0) {
        float n = (float)R_ATOM;
        float mean = red2[0] / n;
        float var  = red[0] / n - mean * mean;
        float sc = atom_gamma[c] * rsqrtf(var + BN_EPS);
        g_scale[0][c] = sc;
        g_shift[0][c] = atom_beta[c] - mean * sc;
    }
}

// ---------------- finalize nei scale (cross via Sab) -----------------------
__global__ void finalize_nei_kernel(const float* __restrict__ nei_W,
                                    const float* __restrict__ nei_gamma,
                                    const float* __restrict__ nei_beta)
{
    const int c = blockIdx.x;
    const int t = threadIdx.x;    // 64 threads
    __shared__ float wb[32];
    __shared__ float red[64];
    if (t < 32) wb[t] = nei_W[c * 96 + 64 + t];
    __syncthreads();
    float v = 0.f;
    #pragma unroll
    for (int j = 0; j < 32; ++j) v += g_Sab[t * 32 + j] * wb[j];
    red[t] = v * nei_W[c * 96 + t];
    __syncthreads();
    for (int s = 32; s > 0; s >>= 1) {
        if (t < s) red[t] += red[t + s];
        __syncthreads();
    }
    if (t == 0) {
        float cross = red[0];
        float n = (float)R_NEI;
        float mean = g_sum1[c] / n;
        float var  = (g_sq1[c] + 2.f * cross) / n - mean * mean;
        float sc = nei_gamma[c] * rsqrtf(var + BN_EPS);
        g_scale[1][c] = sc;
        g_shift[1][c] = nei_beta[c] - mean * sc;
    }
}

// ---------------- nei output: smem-cached P/Q channel-quarters -------------
__global__ __launch_bounds__(512, 2)
void nei_out_kernel(const int* __restrict__ nl, const int* __restrict__ bl,
                    float* __restrict__ out_nei)
{
    extern __shared__ float4 sm4[];
    float4* ps = sm4;                     // 128*16
    float4* qs = sm4 + 128*16;            // 256*16
    int*    sidx = (int*)(qs + 256*16);   // 2048

    const int tid  = threadIdx.x;
    const int blk  = blockIdx.x;
    const int b    = blk >> 2;
    const int qt   = blk & 3;
    const int lane = tid & 31;
    const int warp = tid >> 5;
    const int c16  = lane & 15;

    const float4* P4 = (const float4*)g_P;
    const float4* Q4 = (const float4*)g_Q;

    for (int i = tid; i < 128*16; i += 512) {
        int a = i >> 4, q = i & 15;
        ps[i] = P4[(size_t)(b*128 + a)*64 + qt*16 + q];
    }
    for (int i = tid; i < 256*16; i += 512) {
        int bd = i >> 4, q = i & 15;
        qs[i] = Q4[(size_t)(b*256 + bd)*64 + qt*16 + q];
    }
    for (int i = tid; i < 2048; i += 512) {
        int r = b*2048 + i;
        sidx[i] = nl[r] | (bl[r] << 8);
    }
    float4 s = ((const float4*)g_scale[1])[qt*16 + c16];
    float4 h = ((const float4*)g_shift[1])[qt*16 + c16];
    __syncthreads();

    for (int rp = warp; rp < 1024; rp += 16) {
        int row = rp * 2 + (lane >> 4);
        int pk = sidx[row];
        float4 p = ps[(pk & 255) * 16 + c16];
        float4 q = qs[(pk >> 8) * 16 + c16];
        float4 v;
        v.x = (p.x + q.x) * s.x + h.x;
        v.y = (p.y + q.y) * s.y + h.y;
        v.z = (p.z + q.z) * s.z + h.z;
        v.w = (p.w + q.w) * s.w + h.w;
        v.x = fmaxf(v.x, SLOPE * v.x);
        v.y = fmaxf(v.y, SLOPE * v.y);
        v.z = fmaxf(v.z, SLOPE * v.z);
        v.w = fmaxf(v.w, SLOPE * v.w);
        __stcs((float4*)&out_nei[(size_t)(b*2048 + row)*256 + qt*64 + c16*4], v);
    }
}

// ---------------- launcher ------------------------------------------------
extern "C" void kernel_launch(void* const* d_in, const int* in_sizes, int n_in,
                              void* d_out, int out_size) {
    const float* atom_features = (const float*)d_in[0];
    const float* bond_features = (const float*)d_in[1];
    const int*   atom_nl       = (const int*)  d_in[2];
    const int*   bond_nl       = (const int*)  d_in[3];
    const float* atom_W        = (const float*)d_in[4];
    const float* atom_gamma    = (const float*)d_in[6];
    const float* atom_beta     = (const float*)d_in[7];
    const float* nei_W         = (const float*)d_in[8];
    const float* nei_gamma     = (const float*)d_in[10];
    const float* nei_beta      = (const float*)d_in[11];

    float* out_atom = (float*)d_out;
    float* out_nei  = (float*)d_out + ATOM_OUT_ELEMS;

    const int smemPre = 32 * 64 * (int)sizeof(float);            // 8192
    const int smemMid = SMEM_MID_F * (int)sizeof(float);         // 99328
    const int smemOut = (128*16 + 256*16) * 16 + 2048 * 4;       // 106496
    cudaFuncSetAttribute((const void*)prelude_kernel,
                         cudaFuncAttributeMaxDynamicSharedMemorySize, smemPre);
    cudaFuncSetAttribute((const void*)mid_kernel,
                         cudaFuncAttributeMaxDynamicSharedMemorySize, smemMid);
    cudaFuncSetAttribute((const void*)nei_out_kernel,
                         cudaFuncAttributeMaxDynamicSharedMemorySize, smemOut);

    // 1) zero accumulators
    zero_kernel<<<1, 256>>>();

    // 2) per-batch counts + CSR | atom feature moments (Sx, mx)
    prelude_kernel<<<512, 256, smemPre>>>(atom_nl, bond_nl,
                                          (const float4*)atom_features);

    // 3) atom scale/shift (analytic quadratic form)
    finalize_atom_kernel<<<256, 64>>>(atom_W, atom_gamma, atom_beta);

    // 4) crossdot (Sab) | P-GEMM+wstats | Q-GEMM+wstats | atom GEMM+norm
    mid_kernel<<<2304, 256, smemMid>>>(
        (const float4*)atom_features, (const float4*)bond_features,
        (const float4*)atom_W, (const float4*)nei_W, out_atom);

    // 5) nei scale/shift (cross term via Sab quadratic form)
    finalize_nei_kernel<<<256, 64>>>(nei_W, nei_gamma, nei_beta);

    // 6) nei output: fused gather + normalize + leaky, streaming stores
    nei_out_kernel<<<1024, 512, smemOut>>>(atom_nl, bond_nl, out_nei);
}